// round 4
// baseline (speedup 1.0000x reference)
#include <cuda_runtime.h>
#include <math.h>
#include <stdint.h>

#define NB        15
#define C         50
#define ROW_B     200                 // 50 floats
#define TILE_ROWS 256
#define TILE_B    (TILE_ROWS * ROW_B) // 51200
#define NSTAGE    2
#define THREADS   256
#define GRID      296                 // 2 blocks/SM * 148

// dynamic smem layout
#define SM_DATA   0
#define SM_BAR    (NSTAGE * TILE_B)          // 102400, 2 * 8B
#define SM_BINS   (SM_BAR + NSTAGE * 8)      // 102416, 15 * 8B
#define SM_TOTAL  (SM_BINS + NB * 8)         // 102536

// Global scratch (allocation-free): per-bin totals.
__device__ unsigned long long g_cnt[NB];
__device__ unsigned long long g_acc[NB];
__device__ double             g_conf[NB];

__global__ void ece_zero_kernel() {
    int i = threadIdx.x;
    if (i < NB) { g_cnt[i] = 0ULL; g_acc[i] = 0ULL; g_conf[i] = 0.0; }
}

__device__ __forceinline__ uint32_t smem_u32(const void* p) {
    uint32_t a;
    asm("{ .reg .u64 t; cvta.to.shared.u64 t, %1; cvt.u32.u64 %0, t; }" : "=r"(a) : "l"(p));
    return a;
}

__device__ __forceinline__ void mbar_init(uint32_t mbar, uint32_t cnt) {
    asm volatile("mbarrier.init.shared.b64 [%0], %1;" :: "r"(mbar), "r"(cnt) : "memory");
}

__device__ __forceinline__ void tma_issue(uint32_t dst, const void* src, uint32_t bytes, uint32_t mbar) {
    asm volatile("mbarrier.arrive.expect_tx.shared.b64 _, [%0], %1;" :: "r"(mbar), "r"(bytes) : "memory");
    asm volatile("cp.async.bulk.shared::cluster.global.mbarrier::complete_tx::bytes [%0], [%1], %2, [%3];"
                 :: "r"(dst), "l"(src), "r"(bytes), "r"(mbar) : "memory");
}

__device__ __forceinline__ void mbar_wait(uint32_t mbar, uint32_t parity) {
    uint32_t done;
    asm volatile(
        "{\n\t.reg .pred p;\n\t"
        "mbarrier.try_wait.parity.acquire.cta.shared::cta.b64 p, [%1], %2;\n\t"
        "selp.b32 %0, 1, 0, p;\n\t}"
        : "=r"(done) : "r"(mbar), "r"(parity) : "memory");
    if (!done) {
        asm volatile(
            "{\n\t.reg .pred P1;\n\t"
            "W_%=:\n\t"
            "mbarrier.try_wait.parity.acquire.cta.shared::cta.b64 P1, [%0], %1, 0x989680;\n\t"
            "@P1 bra.uni D_%=;\n\t"
            "bra.uni W_%=;\n\t"
            "D_%=:\n\t}"
            :: "r"(mbar), "r"(parity) : "memory");
    }
}

__device__ __forceinline__ float ex2_approx(float x) {
    float r; asm("ex2.approx.f32 %0, %1;" : "=f"(r) : "f"(x)); return r;
}
__device__ __forceinline__ float rcp_approx(float x) {
    float r; asm("rcp.approx.f32 %0, %1;" : "=f"(r) : "f"(x)); return r;
}

__global__ void __launch_bounds__(THREADS, 2)
ece_main_kernel(const float* __restrict__ logits,
                const int* __restrict__ labels,   // JAX x64-disabled: int32 buffer
                int n)
{
    extern __shared__ char smem[];
    unsigned long long* s_bins = (unsigned long long*)(smem + SM_BINS);
    const uint32_t bar_base = smem_u32(smem + SM_BAR);
    const uint32_t data_base = smem_u32(smem + SM_DATA);

    const int tid = threadIdx.x;
    const int ntiles = (n + TILE_ROWS - 1) / TILE_ROWS;

    if (tid < NB) s_bins[tid] = 0ULL;
    if (tid == 0) {
        #pragma unroll
        for (int s = 0; s < NSTAGE; s++) mbar_init(bar_base + s * 8, 1);
    }
    __syncthreads();

    // ---- prologue: prefetch first NSTAGE tiles ----
    if (tid == 0) {
        #pragma unroll
        for (int s = 0; s < NSTAGE; s++) {
            int t = blockIdx.x + s * GRID;
            if (t < ntiles) {
                int rows = min(TILE_ROWS, n - t * TILE_ROWS);
                uint32_t bytes = ((uint32_t)rows * ROW_B) & ~15u;
                tma_issue(data_base + s * TILE_B,
                          logits + (size_t)t * TILE_ROWS * C, bytes, bar_base + s * 8);
            }
        }
    }

    const float L2E = 1.442695040888963f;
    int k = 0;
    for (int t = blockIdx.x; t < ntiles; t += GRID, k++) {
        const int s = k % NSTAGE;
        const uint32_t parity = (k / NSTAGE) & 1;
        mbar_wait(bar_base + s * 8, parity);

        const int rows_here = min(TILE_ROWS, n - t * TILE_ROWS);
        const int row = t * TILE_ROWS + tid;
        if (row < n) {
            const bool full = (rows_here == TILE_ROWS);
            const char* rbase = smem + SM_DATA + s * TILE_B + tid * ROW_B;

            float vals[C];
            if (full) {
                const float2* p = (const float2*)rbase;
                #pragma unroll
                for (int i = 0; i < C / 2; i++) {
                    float2 v = p[i];
                    vals[2 * i] = v.x; vals[2 * i + 1] = v.y;
                }
            } else {
                const float2* p = (const float2*)(logits + (size_t)row * C);
                #pragma unroll
                for (int i = 0; i < C / 2; i++) {
                    float2 v = __ldg(p + i);
                    vals[2 * i] = v.x; vals[2 * i + 1] = v.y;
                }
            }

            // max (FMNMX chain)
            float m = vals[0];
            #pragma unroll
            for (int i = 1; i < C; i++) m = fmaxf(m, vals[i]);

            // accuracy: vals[label] == max  (first-occurrence ties are measure-zero)
            const int lbl = labels[row];
            float vl;
            if (full) vl = *(const float*)(rbase + lbl * 4);
            else      vl = __ldg(logits + (size_t)row * C + lbl);
            const int acc = (vl == m) ? 1 : 0;

            // conf = 1 / sum exp(v - m) ; exp via EX2: FFMA + MUFU + FADD
            const float nfm = -m * L2E;
            float s0 = 0.0f, s1 = 0.0f;
            #pragma unroll
            for (int i = 0; i < C; i += 2) {
                s0 += ex2_approx(fmaf(vals[i],     L2E, nfm));
                s1 += ex2_approx(fmaf(vals[i + 1], L2E, nfm));
            }
            const float conf = rcp_approx(s0 + s1);

            // bin = clip(ceil(conf*15) - 1, 0, 14)
            int bin = (int)ceilf(conf * 15.0f) - 1;
            bin = bin < 0 ? 0 : (bin > NB - 1 ? NB - 1 : bin);

            // packed: conf 2^-24 fixed point [0,38) | acc [38,51) | count [51,64)
            unsigned long long cf = (unsigned long long)(conf * 16777216.0f + 0.5f);
            unsigned long long pack = cf | ((unsigned long long)acc << 38) | (1ULL << 51);
            atomicAdd(&s_bins[bin], pack);
        }

        __syncthreads();   // all reads of stage s done before refill

        if (tid == 0) {
            int tn = t + NSTAGE * GRID;
            if (tn < ntiles) {
                int rows = min(TILE_ROWS, n - tn * TILE_ROWS);
                uint32_t bytes = ((uint32_t)rows * ROW_B) & ~15u;
                tma_issue(data_base + s * TILE_B,
                          logits + (size_t)tn * TILE_ROWS * C, bytes, bar_base + s * 8);
            }
        }
    }

    __syncthreads();
    if (tid < NB) {
        unsigned long long v = s_bins[tid];
        if (v) {
            unsigned long long cf = v & ((1ULL << 38) - 1);
            unsigned long long ac = (v >> 38) & 0x1FFFULL;
            unsigned long long ct = v >> 51;
            atomicAdd(&g_cnt[tid], ct);
            atomicAdd(&g_acc[tid], ac);
            atomicAdd(&g_conf[tid], (double)cf * (1.0 / 16777216.0));
        }
    }
}

__global__ void ece_final_kernel(float* __restrict__ out, int n)
{
    // out layout: [0] ece, [1..15] bin_over_confidence, [16..30] prop_in_bin
    double ece = 0.0;
    for (int i = 0; i < NB; i++) {
        double ct = (double)g_cnt[i];
        double prop = ct / (double)n;
        bool nonempty = ct > 0.0;
        double denom = nonempty ? ct : 1.0;
        double avg_acc  = (double)g_acc[i] / denom;
        double avg_conf = g_conf[i] / denom;
        double gap = avg_conf - avg_acc;
        out[1 + i]  = (float)(nonempty ? gap * prop : 0.0);
        out[16 + i] = (float)prop;
        if (nonempty) ece += fabs(gap) * prop;
    }
    out[0] = (float)ece;
}

extern "C" void kernel_launch(void* const* d_in, const int* in_sizes, int n_in,
                              void* d_out, int out_size)
{
    const float* logits = (const float*)d_in[0];
    const int*   labels = (const int*)d_in[1];
    int n = in_sizes[1];   // label count = number of rows

    static bool attr_set = false;
    if (!attr_set) {
        cudaFuncSetAttribute(ece_main_kernel,
                             cudaFuncAttributeMaxDynamicSharedMemorySize, SM_TOTAL);
        attr_set = true;
    }

    ece_zero_kernel<<<1, 32>>>();
    ece_main_kernel<<<GRID, THREADS, SM_TOTAL>>>(logits, labels, n);
    ece_final_kernel<<<1, 1>>>((float*)d_out, n);
}